// round 4
// baseline (speedup 1.0000x reference)
#include <cuda_runtime.h>

// Point-transformer fused kernel for GB300 (sm_103a).
// B*G = 16384 groups, 16 neighbors, dim 3.
// 32 threads per group (thread = (point i, j-half)); 4 groups per 128-thread block.
// mlp_w1 / mlp_w2 read from global (L1-resident), phase 5 uses float2 columns.
// Target 8 resident blocks (64 regs).

#define GPB 4
#define NTHR 128
#define NBLOCKS (16384 / GPB)
#define ASTRIDE 68  // 64 + 4 pad

// ---- shared memory layout (float offsets) ----
#define OFF_WQKV 0      // 27
#define OFF_PW1  32     // 192
#define OFF_PB1  224    // 64   (16B aligned)
#define OFF_PW2  288    // 192  (16B aligned)
#define OFF_PB2  480    // 3
#define OFF_AW1  484    // 36
#define OFF_AB1  520    // 12
#define OFF_AW2  532    // 36
#define OFF_AB2  568    // 3
#define OFF_MB1  572    // 48
#define OFF_MB2  620    // 48
#define OFF_MW3  668    // 48
#define OFF_MB3  716    // 1
#define OFF_A    720    // GPB * 16 * ASTRIDE = 4352
#define OFF_K    (OFF_A + GPB * 16 * ASTRIDE)   // GPB*48
#define OFF_KV   (OFF_K + GPB * 48)             // GPB*48
#define OFF_SA   (OFF_KV + GPB * 48)            // GPB*48
#define OFF_H1   (OFF_SA + GPB * 48)            // GPB*48
#define SMEM_FLOATS (OFF_H1 + GPB * 48)         // 5840 floats = 23.36 KB

#define LOADW(PTR, OFF, N)                                        \
    for (int idx_ = tid; idx_ < (N); idx_ += NTHR) sm[(OFF) + idx_] = (PTR)[idx_];

__global__ __launch_bounds__(NTHR, 8)
void pt_kernel(const float* __restrict__ data,
               const float* __restrict__ wqkv,
               const float* __restrict__ pw1, const float* __restrict__ pb1,
               const float* __restrict__ pw2, const float* __restrict__ pb2,
               const float* __restrict__ aw1, const float* __restrict__ ab1,
               const float* __restrict__ aw2, const float* __restrict__ ab2,
               const float* __restrict__ mw1, const float* __restrict__ mb1,
               const float* __restrict__ mw2, const float* __restrict__ mb2,
               const float* __restrict__ mw3, const float* __restrict__ mb3,
               float* __restrict__ out)
{
    extern __shared__ float sm[];
    const int tid = threadIdx.x;
    const int g = tid >> 5;     // group = warp
    const int lg = tid & 31;    // lane in group
    const int i = lg & 15;      // point index
    const int half = lg >> 4;   // which 8 j's this thread owns

    // ---- phase 1a: stage only the SMALL weights into shared ----
    LOADW(wqkv, OFF_WQKV, 27)
    LOADW(pw1, OFF_PW1, 192)
    LOADW(pb1, OFF_PB1, 64)
    LOADW(pw2, OFF_PW2, 192)
    LOADW(pb2, OFF_PB2, 3)
    LOADW(aw1, OFF_AW1, 36)
    LOADW(ab1, OFF_AB1, 12)
    LOADW(aw2, OFF_AW2, 36)
    LOADW(ab2, OFF_AB2, 3)
    LOADW(mb1, OFF_MB1, 48)
    LOADW(mb2, OFF_MB2, 48)
    LOADW(mw3, OFF_MW3, 48)
    LOADW(mb3, OFF_MB3, 1)

    const int bg = blockIdx.x * GPB + g;
    const float* xp = data + (size_t)bg * 48 + i * 3;
    const float x0 = xp[0], x1 = xp[1], x2 = xp[2];

    __syncthreads();

    // ---- phase 1b: per-point q,k,v; pos-hidden a[i][h] (each half does 32 h) ----
    const float* W = sm + OFF_WQKV;  // [3][9]: q cols 0-2, k 3-5, v 6-8
    const float q0 = fmaf(x2, W[18 + 0], fmaf(x1, W[9 + 0], x0 * W[0]));
    const float q1 = fmaf(x2, W[18 + 1], fmaf(x1, W[9 + 1], x0 * W[1]));
    const float q2 = fmaf(x2, W[18 + 2], fmaf(x1, W[9 + 2], x0 * W[2]));
    const float k0 = fmaf(x2, W[18 + 3], fmaf(x1, W[9 + 3], x0 * W[3]));
    const float k1 = fmaf(x2, W[18 + 4], fmaf(x1, W[9 + 4], x0 * W[4]));
    const float k2 = fmaf(x2, W[18 + 5], fmaf(x1, W[9 + 5], x0 * W[5]));
    const float v0 = fmaf(x2, W[18 + 6], fmaf(x1, W[9 + 6], x0 * W[6]));
    const float v1 = fmaf(x2, W[18 + 7], fmaf(x1, W[9 + 7], x0 * W[7]));
    const float v2 = fmaf(x2, W[18 + 8], fmaf(x1, W[9 + 8], x0 * W[8]));

    if (half == 0) {
        float* kW = sm + OFF_K + g * 48 + i * 3;
        kW[0] = k0; kW[1] = k1; kW[2] = k2;
        float* kvW = sm + OFF_KV + g * 48 + i * 3;
        kvW[0] = k0 + v0; kvW[1] = k1 + v1; kvW[2] = k2 + v2;
    }
    {
        float* aW = sm + OFF_A + (g * 16 + i) * ASTRIDE + half * 32;
        const float* P1 = sm + OFF_PW1 + half * 32;  // [3][64] slice
        #pragma unroll 8
        for (int h = 0; h < 32; h++) {
            aW[h] = fmaf(x2, P1[128 + h], fmaf(x1, P1[64 + h], x0 * P1[h]));
        }
    }
    __syncthreads();

    // ---- phase 2: rel_emb for this thread's 8 j's (re[jj][3] in registers) ----
    float re[24];
    {
        const float pb20 = sm[OFF_PB2 + 0], pb21 = sm[OFF_PB2 + 1], pb22 = sm[OFF_PB2 + 2];
        #pragma unroll
        for (int jj = 0; jj < 8; jj++) {
            re[jj * 3 + 0] = pb20; re[jj * 3 + 1] = pb21; re[jj * 3 + 2] = pb22;
        }
    }
    {
        const float4* aJ = (const float4*)(sm + OFF_A + (g * 16 + half * 8) * ASTRIDE);
        const float4* aI = (const float4*)(sm + OFF_A + (g * 16 + i) * ASTRIDE);
        const float4* b1v4 = (const float4*)(sm + OFF_PB1);
        const float4* w2v4 = (const float4*)(sm + OFF_PW2);
        #pragma unroll 1
        for (int hq = 0; hq < 16; hq++) {
            const float4 ai = aI[hq];
            const float4 bb = b1v4[hq];
            const float ai0 = ai.x + bb.x, ai1 = ai.y + bb.y;
            const float ai2 = ai.z + bb.z, ai3 = ai.w + bb.w;
            const float4 wA = w2v4[hq * 3 + 0];
            const float4 wB = w2v4[hq * 3 + 1];
            const float4 wC = w2v4[hq * 3 + 2];
            #pragma unroll
            for (int jj = 0; jj < 8; jj++) {
                const float4 aj = aJ[jj * (ASTRIDE / 4) + hq];
                const float e0 = fmaxf(ai0 - aj.x, 0.f);
                const float e1 = fmaxf(ai1 - aj.y, 0.f);
                const float e2 = fmaxf(ai2 - aj.z, 0.f);
                const float e3 = fmaxf(ai3 - aj.w, 0.f);
                float r0 = re[jj * 3 + 0], r1 = re[jj * 3 + 1], r2 = re[jj * 3 + 2];
                r0 = fmaf(e0, wA.x, r0); r1 = fmaf(e0, wA.y, r1); r2 = fmaf(e0, wA.z, r2);
                r0 = fmaf(e1, wA.w, r0); r1 = fmaf(e1, wB.x, r1); r2 = fmaf(e1, wB.y, r2);
                r0 = fmaf(e2, wB.z, r0); r1 = fmaf(e2, wB.w, r1); r2 = fmaf(e2, wC.x, r2);
                r0 = fmaf(e3, wC.y, r0); r1 = fmaf(e3, wC.z, r1); r2 = fmaf(e3, wC.w, r2);
                re[jj * 3 + 0] = r0; re[jj * 3 + 1] = r1; re[jj * 3 + 2] = r2;
            }
        }
    }

    // ---- phase 3: t = q_i - k_j + rel_emb; attention MLP 3->12->3 ----
    const float* kS  = sm + OFF_K  + g * 48 + half * 24;
    const float* kvS = sm + OFF_KV + g * 48 + half * 24;
    #pragma unroll
    for (int jj = 0; jj < 8; jj++) {
        re[jj * 3 + 0] += q0 - kS[jj * 3 + 0];
        re[jj * 3 + 1] += q1 - kS[jj * 3 + 1];
        re[jj * 3 + 2] += q2 - kS[jj * 3 + 2];
    }
    float sim[24];
    {
        const float ab20 = sm[OFF_AB2 + 0], ab21 = sm[OFF_AB2 + 1], ab22 = sm[OFF_AB2 + 2];
        #pragma unroll
        for (int jj = 0; jj < 8; jj++) {
            sim[jj * 3 + 0] = ab20; sim[jj * 3 + 1] = ab21; sim[jj * 3 + 2] = ab22;
        }
    }
    #pragma unroll 1
    for (int c = 0; c < 12; c++) {
        const float w10 = sm[OFF_AW1 + c];
        const float w11 = sm[OFF_AW1 + 12 + c];
        const float w12 = sm[OFF_AW1 + 24 + c];
        const float bb = sm[OFF_AB1 + c];
        const float w20 = sm[OFF_AW2 + c * 3 + 0];
        const float w21 = sm[OFF_AW2 + c * 3 + 1];
        const float w22 = sm[OFF_AW2 + c * 3 + 2];
        #pragma unroll
        for (int jj = 0; jj < 8; jj++) {
            float u = fmaf(re[jj * 3 + 2], w12,
                     fmaf(re[jj * 3 + 1], w11,
                     fmaf(re[jj * 3 + 0], w10, bb)));
            u = fmaxf(u, 0.f);
            sim[jj * 3 + 0] = fmaf(u, w20, sim[jj * 3 + 0]);
            sim[jj * 3 + 1] = fmaf(u, w21, sim[jj * 3 + 1]);
            sim[jj * 3 + 2] = fmaf(u, w22, sim[jj * 3 + 2]);
        }
    }

    // ---- phase 4: softmax over 16 j (8 local + partner half via shfl) ----
    float agg[3];
    #pragma unroll
    for (int d = 0; d < 3; d++) {
        const float qd = (d == 0) ? q0 : ((d == 1) ? q1 : q2);
        float pm = sim[d];
        #pragma unroll
        for (int jj = 1; jj < 8; jj++) pm = fmaxf(pm, sim[jj * 3 + d]);
        const float m = fmaxf(pm, __shfl_xor_sync(0xffffffffu, pm, 16));
        float s = 0.f, acc = 0.f;
        #pragma unroll
        for (int jj = 0; jj < 8; jj++) {
            const float p = __expf(sim[jj * 3 + d] - m);
            s += p;
            // v_ij = v_j + rel_emb = t + (k_j + v_j) - q_i
            const float vij = re[jj * 3 + d] + kvS[jj * 3 + d] - qd;
            acc = fmaf(p, vij, acc);
        }
        s   += __shfl_xor_sync(0xffffffffu, s, 16);
        acc += __shfl_xor_sync(0xffffffffu, acc, 16);
        agg[d] = __fdividef(acc, s);
    }
    if (half == 0) {
        float* saW = sm + OFF_SA + g * 48 + i * 3;
        saW[0] = agg[0]; saW[1] = agg[1]; saW[2] = agg[2];
    }
    __syncwarp();

    // ---- phase 5: MLP head 48->48->48->1 ----
    // Lanes 0..23 each own a float2 column pair (2*lg, 2*lg+1); W1/W2 via LDG.64.
    const float* saS = sm + OFF_SA + g * 48;
    const int c = 2 * lg;
    float2 h1 = make_float2(0.f, 0.f);
    if (lg < 24) {
        h1.x = sm[OFF_MB1 + c]; h1.y = sm[OFF_MB1 + c + 1];
        #pragma unroll 4
        for (int kk = 0; kk < 48; kk++) {
            const float sv = saS[kk];
            const float2 w = __ldg((const float2*)(mw1 + kk * 48 + c));
            h1.x = fmaf(sv, w.x, h1.x);
            h1.y = fmaf(sv, w.y, h1.y);
        }
        h1.x = fmaxf(h1.x, 0.f); h1.y = fmaxf(h1.y, 0.f);
        *(float2*)(sm + OFF_H1 + g * 48 + c) = h1;
    }
    __syncwarp();

    const float* h1S = sm + OFF_H1 + g * 48;
    float pw = 0.f;
    if (lg < 24) {
        float2 h2 = make_float2(sm[OFF_MB2 + c], sm[OFF_MB2 + c + 1]);
        #pragma unroll 4
        for (int kk = 0; kk < 48; kk++) {
            const float hv = h1S[kk];
            const float2 w = __ldg((const float2*)(mw2 + kk * 48 + c));
            h2.x = fmaf(hv, w.x, h2.x);
            h2.y = fmaf(hv, w.y, h2.y);
        }
        h2.x = fmaxf(h2.x, 0.f); h2.y = fmaxf(h2.y, 0.f);
        pw = fmaf(h2.y, sm[OFF_MW3 + c + 1], h2.x * sm[OFF_MW3 + c]);
    }
    pw += __shfl_xor_sync(0xffffffffu, pw, 16);
    pw += __shfl_xor_sync(0xffffffffu, pw, 8);
    pw += __shfl_xor_sync(0xffffffffu, pw, 4);
    pw += __shfl_xor_sync(0xffffffffu, pw, 2);
    pw += __shfl_xor_sync(0xffffffffu, pw, 1);
    if (lg == 0) out[bg] = pw + sm[OFF_MB3];
}

extern "C" void kernel_launch(void* const* d_in, const int* in_sizes, int n_in,
                              void* d_out, int out_size) {
    // metadata order: original_points(unused), data, w_qkv, pos_w1, pos_b1, pos_w2,
    // pos_b2, attn_w1, attn_b1, attn_w2, attn_b2, mlp_w1, mlp_b1, mlp_w2, mlp_b2,
    // mlp_w3, mlp_b3
    const float* data = (const float*)d_in[1];
    const float* wqkv = (const float*)d_in[2];
    const float* pw1  = (const float*)d_in[3];
    const float* pb1  = (const float*)d_in[4];
    const float* pw2  = (const float*)d_in[5];
    const float* pb2  = (const float*)d_in[6];
    const float* aw1  = (const float*)d_in[7];
    const float* ab1  = (const float*)d_in[8];
    const float* aw2  = (const float*)d_in[9];
    const float* ab2  = (const float*)d_in[10];
    const float* mw1  = (const float*)d_in[11];
    const float* mb1  = (const float*)d_in[12];
    const float* mw2  = (const float*)d_in[13];
    const float* mb2  = (const float*)d_in[14];
    const float* mw3  = (const float*)d_in[15];
    const float* mb3  = (const float*)d_in[16];
    float* out = (float*)d_out;

    const size_t smem = SMEM_FLOATS * sizeof(float);  // ~23.4 KB
    pt_kernel<<<NBLOCKS, NTHR, smem>>>(data, wqkv, pw1, pb1, pw2, pb2,
                                       aw1, ab1, aw2, ab2,
                                       mw1, mb1, mw2, mb2, mw3, mb3, out);
}

// round 5
// speedup vs baseline: 1.0634x; 1.0634x over previous
#include <cuda_runtime.h>

// Point-transformer fused kernel for GB300 (sm_103a).
// B*G = 16384 groups, 16 neighbors, dim 3.
// 32 threads per group (thread = (point i, j-half = 4 j-pairs)).
// Phases 2-3 use packed f32x2 (FFMA2/FADD2) across neighbor pairs.
// j-side pos-hidden array stored NEGATED + pair-interleaved so subtraction
// becomes add.rn.f32x2 (only attested packed ops used).

#define GPB 4
#define NTHR 128
#define NBLOCKS (16384 / GPB)
#define SROW 132          // floats per j-pair row: 64*2 + 4 pad
#define SGRP (8 * SROW)   // 1056 floats per group

// ---- shared memory layout (float offsets) ----
#define OFF_WQKV 0       // 27
#define OFF_PW1  32      // 192
#define OFF_PB1  224     // 64
#define OFF_PW2D 288     // 384: dup pairs, d-major: (d*64+h)*2+par
#define OFF_PB2D 672     // 6
#define OFF_AW1D 680     // 72: (d*12+c)*2+par
#define OFF_AB1D 752     // 24
#define OFF_AW2D 776     // 72: (c*3+d)*2+par
#define OFF_AB2D 848     // 6
#define OFF_MB1  856     // 48
#define OFF_MB2  904     // 48
#define OFF_MW3  952     // 48
#define OFF_MB3  1000    // 1
#define OFF_S    1004    // 4 groups * 1056 = 4224 (float4-aligned: 1004%4==0)
#define OFF_NK   (OFF_S + GPB * SGRP)   // neg-k interleaved: (jp*3+d)*2+par; GPB*48
#define OFF_KV   (OFF_NK + GPB * 48)    // k+v scalar [j][d]; GPB*48
#define OFF_SA   (OFF_KV + GPB * 48)    // GPB*48
#define OFF_H1   (OFF_SA + GPB * 48)    // GPB*48
#define SMEM_FLOATS (OFF_H1 + GPB * 48) // 5996 floats = 23.98 KB

__device__ __forceinline__ float2 add2(float2 a, float2 b) {
    float2 r;
    asm("add.rn.f32x2 %0, %1, %2;"
        : "=l"(*reinterpret_cast<unsigned long long*>(&r))
        : "l"(*reinterpret_cast<unsigned long long*>(&a)),
          "l"(*reinterpret_cast<unsigned long long*>(&b)));
    return r;
}
__device__ __forceinline__ float2 fma2(float2 a, float2 b, float2 c) {
    float2 r;
    asm("fma.rn.f32x2 %0, %1, %2, %3;"
        : "=l"(*reinterpret_cast<unsigned long long*>(&r))
        : "l"(*reinterpret_cast<unsigned long long*>(&a)),
          "l"(*reinterpret_cast<unsigned long long*>(&b)),
          "l"(*reinterpret_cast<unsigned long long*>(&c)));
    return r;
}

#define LOADW(PTR, OFF, N)                                        \
    for (int idx_ = tid; idx_ < (N); idx_ += NTHR) sm[(OFF) + idx_] = (PTR)[idx_];
#define LOADDUP(PTR, OFF, N2)                                     \
    for (int idx_ = tid; idx_ < (N2); idx_ += NTHR) sm[(OFF) + idx_] = (PTR)[idx_ >> 1];

__global__ __launch_bounds__(NTHR, 7)
void pt_kernel(const float* __restrict__ data,
               const float* __restrict__ wqkv,
               const float* __restrict__ pw1, const float* __restrict__ pb1,
               const float* __restrict__ pw2, const float* __restrict__ pb2,
               const float* __restrict__ aw1, const float* __restrict__ ab1,
               const float* __restrict__ aw2, const float* __restrict__ ab2,
               const float* __restrict__ mw1, const float* __restrict__ mb1,
               const float* __restrict__ mw2, const float* __restrict__ mb2,
               const float* __restrict__ mw3, const float* __restrict__ mb3,
               float* __restrict__ out)
{
    extern __shared__ float sm[];
    const int tid = threadIdx.x;
    const int g = tid >> 5;     // group = warp
    const int lg = tid & 31;    // lane in group
    const int i = lg & 15;      // point index
    const int half = lg >> 4;   // which 4 j-pairs this thread owns

    // ---- phase 1a: stage small weights (dup-pair layouts for packed math) ----
    LOADW(wqkv, OFF_WQKV, 27)
    LOADW(pw1, OFF_PW1, 192)
    LOADW(pb1, OFF_PB1, 64)
    // PW2D: d-major dup: (d*64+h)*2+par <- pw2[h*3+d]
    for (int idx_ = tid; idx_ < 384; idx_ += NTHR) {
        const int d = idx_ >> 7, rem = idx_ & 127, h = rem >> 1;
        sm[OFF_PW2D + idx_] = pw2[h * 3 + d];
    }
    LOADDUP(pb2, OFF_PB2D, 6)
    LOADDUP(aw1, OFF_AW1D, 72)
    LOADDUP(ab1, OFF_AB1D, 24)
    LOADDUP(aw2, OFF_AW2D, 72)
    LOADDUP(ab2, OFF_AB2D, 6)
    LOADW(mb1, OFF_MB1, 48)
    LOADW(mb2, OFF_MB2, 48)
    LOADW(mw3, OFF_MW3, 48)
    LOADW(mb3, OFF_MB3, 1)

    const int bg = blockIdx.x * GPB + g;
    const float* xp = data + (size_t)bg * 48 + i * 3;
    const float x0 = xp[0], x1 = xp[1], x2 = xp[2];

    __syncthreads();

    // ---- phase 1b: q,k,v; negated pos-hidden into pair-interleaved S ----
    const float* W = sm + OFF_WQKV;  // [3][9]: q 0-2, k 3-5, v 6-8
    const float q0 = fmaf(x2, W[18 + 0], fmaf(x1, W[9 + 0], x0 * W[0]));
    const float q1 = fmaf(x2, W[18 + 1], fmaf(x1, W[9 + 1], x0 * W[1]));
    const float q2 = fmaf(x2, W[18 + 2], fmaf(x1, W[9 + 2], x0 * W[2]));
    const float k0 = fmaf(x2, W[18 + 3], fmaf(x1, W[9 + 3], x0 * W[3]));
    const float k1 = fmaf(x2, W[18 + 4], fmaf(x1, W[9 + 4], x0 * W[4]));
    const float k2 = fmaf(x2, W[18 + 5], fmaf(x1, W[9 + 5], x0 * W[5]));
    const float v0 = fmaf(x2, W[18 + 6], fmaf(x1, W[9 + 6], x0 * W[6]));
    const float v1 = fmaf(x2, W[18 + 7], fmaf(x1, W[9 + 7], x0 * W[7]));
    const float v2 = fmaf(x2, W[18 + 8], fmaf(x1, W[9 + 8], x0 * W[8]));

    const int jp_own = i >> 1, par_own = i & 1;
    if (half == 0) {
        float* nk = sm + OFF_NK + g * 48;
        nk[(jp_own * 3 + 0) * 2 + par_own] = -k0;
        nk[(jp_own * 3 + 1) * 2 + par_own] = -k1;
        nk[(jp_own * 3 + 2) * 2 + par_own] = -k2;
        float* kvW = sm + OFF_KV + g * 48 + i * 3;
        kvW[0] = k0 + v0; kvW[1] = k1 + v1; kvW[2] = k2 + v2;
    }
    {
        // S[jp][h][2] = -(a_j[h]); this thread writes h in [half*32, half*32+32)
        float* Sw = sm + OFF_S + g * SGRP + jp_own * SROW + par_own + half * 64;
        const float* P1 = sm + OFF_PW1 + half * 32;
        #pragma unroll 8
        for (int h = 0; h < 32; h++) {
            const float na = fmaf(-x2, P1[128 + h], fmaf(-x1, P1[64 + h], -x0 * P1[h]));
            Sw[h * 2] = na;
        }
    }
    __syncthreads();

    // ---- phase 2: packed rel_emb accumulation over this thread's 4 j-pairs ----
    float2 re2[12];  // [d*4 + jpl]
    {
        const float2* pb2d = (const float2*)(sm + OFF_PB2D);
        const float2 r0 = pb2d[0], r1 = pb2d[1], r2v = pb2d[2];
        #pragma unroll
        for (int jpl = 0; jpl < 4; jpl++) {
            re2[0 + jpl] = r0; re2[4 + jpl] = r1; re2[8 + jpl] = r2v;
        }
    }
    {
        const float* Sg = sm + OFF_S + g * SGRP;
        const float* Si = Sg + (i >> 1) * SROW + (i & 1);
        const float* Sjb = Sg + (half * 4) * SROW;
        #pragma unroll 2
        for (int hp = 0; hp < 32; hp++) {   // h-pair: h = 2*hp, 2*hp+1
            const float2 bb = *(const float2*)(sm + OFF_PB1 + hp * 2);
            const float a0 = bb.x - Si[hp * 4];      // a_i[2hp] + b
            const float a1 = bb.y - Si[hp * 4 + 2];  // a_i[2hp+1] + b
            const float2 ai0 = make_float2(a0, a0);
            const float2 ai1 = make_float2(a1, a1);
            // dup W2 for this h-pair, per output d
            const float4 w0 = *(const float4*)(sm + OFF_PW2D + 0 * 128 + hp * 4);
            const float4 w1 = *(const float4*)(sm + OFF_PW2D + 1 * 128 + hp * 4);
            const float4 w2 = *(const float4*)(sm + OFF_PW2D + 2 * 128 + hp * 4);
            #pragma unroll
            for (int jpl = 0; jpl < 4; jpl++) {
                const float4 s = *(const float4*)(Sjb + jpl * SROW + hp * 4);
                float2 e0 = add2(ai0, make_float2(s.x, s.y));   // a_i - a_j + b (2 j's)
                e0.x = fmaxf(e0.x, 0.f); e0.y = fmaxf(e0.y, 0.f);
                float2 e1 = add2(ai1, make_float2(s.z, s.w));
                e1.x = fmaxf(e1.x, 0.f); e1.y = fmaxf(e1.y, 0.f);
                re2[0 + jpl] = fma2(e0, make_float2(w0.x, w0.y), re2[0 + jpl]);
                re2[4 + jpl] = fma2(e0, make_float2(w1.x, w1.y), re2[4 + jpl]);
                re2[8 + jpl] = fma2(e0, make_float2(w2.x, w2.y), re2[8 + jpl]);
                re2[0 + jpl] = fma2(e1, make_float2(w0.z, w0.w), re2[0 + jpl]);
                re2[4 + jpl] = fma2(e1, make_float2(w1.z, w1.w), re2[4 + jpl]);
                re2[8 + jpl] = fma2(e1, make_float2(w2.z, w2.w), re2[8 + jpl]);
            }
        }
    }

    // ---- phase 3: t = re + q - k (packed); attention MLP 3->12->3 (packed) ----
    {
        const float2* nkg = (const float2*)(sm + OFF_NK + g * 48);
        const float2 q2d0 = make_float2(q0, q0);
        const float2 q2d1 = make_float2(q1, q1);
        const float2 q2d2 = make_float2(q2, q2);
        #pragma unroll
        for (int jpl = 0; jpl < 4; jpl++) {
            const int jp = half * 4 + jpl;
            re2[0 + jpl] = add2(re2[0 + jpl], add2(q2d0, nkg[jp * 3 + 0]));
            re2[4 + jpl] = add2(re2[4 + jpl], add2(q2d1, nkg[jp * 3 + 1]));
            re2[8 + jpl] = add2(re2[8 + jpl], add2(q2d2, nkg[jp * 3 + 2]));
        }
    }
    float2 sim2[12];
    {
        const float2* ab2d = (const float2*)(sm + OFF_AB2D);
        const float2 b0 = ab2d[0], b1 = ab2d[1], b2 = ab2d[2];
        #pragma unroll
        for (int jpl = 0; jpl < 4; jpl++) {
            sim2[0 + jpl] = b0; sim2[4 + jpl] = b1; sim2[8 + jpl] = b2;
        }
    }
    {
        const float2* w1d = (const float2*)(sm + OFF_AW1D);
        const float2* b1d = (const float2*)(sm + OFF_AB1D);
        const float2* w2d = (const float2*)(sm + OFF_AW2D);
        #pragma unroll 2
        for (int c = 0; c < 12; c++) {
            const float2 w10 = w1d[c], w11 = w1d[12 + c], w12 = w1d[24 + c];
            const float2 bbd = b1d[c];
            const float2 w20 = w2d[c * 3 + 0], w21 = w2d[c * 3 + 1], w22 = w2d[c * 3 + 2];
            #pragma unroll
            for (int jpl = 0; jpl < 4; jpl++) {
                float2 u = fma2(re2[8 + jpl], w12,
                          fma2(re2[4 + jpl], w11,
                          fma2(re2[0 + jpl], w10, bbd)));
                u.x = fmaxf(u.x, 0.f); u.y = fmaxf(u.y, 0.f);
                sim2[0 + jpl] = fma2(u, w20, sim2[0 + jpl]);
                sim2[4 + jpl] = fma2(u, w21, sim2[4 + jpl]);
                sim2[8 + jpl] = fma2(u, w22, sim2[8 + jpl]);
            }
        }
    }

    // ---- phase 4: softmax over 16 j (8 local as 4 pairs + partner via shfl) ----
    const float* kvS = sm + OFF_KV + g * 48 + half * 24;
    float agg[3];
    #pragma unroll
    for (int d = 0; d < 3; d++) {
        const float qd = (d == 0) ? q0 : ((d == 1) ? q1 : q2);
        float pm = sim2[d * 4 + 0].x;
        pm = fmaxf(pm, sim2[d * 4 + 0].y);
        #pragma unroll
        for (int jpl = 1; jpl < 4; jpl++) {
            pm = fmaxf(pm, sim2[d * 4 + jpl].x);
            pm = fmaxf(pm, sim2[d * 4 + jpl].y);
        }
        const float m = fmaxf(pm, __shfl_xor_sync(0xffffffffu, pm, 16));
        float s = 0.f, acc = 0.f;
        #pragma unroll
        for (int jpl = 0; jpl < 4; jpl++) {
            float p = __expf(sim2[d * 4 + jpl].x - m);
            s += p;
            float vij = re2[d * 4 + jpl].x + kvS[(jpl * 2) * 3 + d] - qd;
            acc = fmaf(p, vij, acc);
            p = __expf(sim2[d * 4 + jpl].y - m);
            s += p;
            vij = re2[d * 4 + jpl].y + kvS[(jpl * 2 + 1) * 3 + d] - qd;
            acc = fmaf(p, vij, acc);
        }
        s   += __shfl_xor_sync(0xffffffffu, s, 16);
        acc += __shfl_xor_sync(0xffffffffu, acc, 16);
        agg[d] = __fdividef(acc, s);
    }
    if (half == 0) {
        float* saW = sm + OFF_SA + g * 48 + i * 3;
        saW[0] = agg[0]; saW[1] = agg[1]; saW[2] = agg[2];
    }
    __syncwarp();

    // ---- phase 5: MLP head 48->48->48->1; lanes 0..23 own float2 col pairs ----
    const float* saS = sm + OFF_SA + g * 48;
    const int c = 2 * lg;
    float2 h1 = make_float2(0.f, 0.f);
    if (lg < 24) {
        h1.x = sm[OFF_MB1 + c]; h1.y = sm[OFF_MB1 + c + 1];
        #pragma unroll 4
        for (int kk = 0; kk < 48; kk++) {
            const float sv = saS[kk];
            const float2 w = __ldg((const float2*)(mw1 + kk * 48 + c));
            h1.x = fmaf(sv, w.x, h1.x);
            h1.y = fmaf(sv, w.y, h1.y);
        }
        h1.x = fmaxf(h1.x, 0.f); h1.y = fmaxf(h1.y, 0.f);
        *(float2*)(sm + OFF_H1 + g * 48 + c) = h1;
    }
    __syncwarp();

    const float* h1S = sm + OFF_H1 + g * 48;
    float pw = 0.f;
    if (lg < 24) {
        float2 h2 = make_float2(sm[OFF_MB2 + c], sm[OFF_MB2 + c + 1]);
        #pragma unroll 4
        for (int kk = 0; kk < 48; kk++) {
            const float hv = h1S[kk];
            const float2 w = __ldg((const float2*)(mw2 + kk * 48 + c));
            h2.x = fmaf(hv, w.x, h2.x);
            h2.y = fmaf(hv, w.y, h2.y);
        }
        h2.x = fmaxf(h2.x, 0.f); h2.y = fmaxf(h2.y, 0.f);
        pw = fmaf(h2.y, sm[OFF_MW3 + c + 1], h2.x * sm[OFF_MW3 + c]);
    }
    pw += __shfl_xor_sync(0xffffffffu, pw, 16);
    pw += __shfl_xor_sync(0xffffffffu, pw, 8);
    pw += __shfl_xor_sync(0xffffffffu, pw, 4);
    pw += __shfl_xor_sync(0xffffffffu, pw, 2);
    pw += __shfl_xor_sync(0xffffffffu, pw, 1);
    if (lg == 0) out[bg] = pw + sm[OFF_MB3];
}

extern "C" void kernel_launch(void* const* d_in, const int* in_sizes, int n_in,
                              void* d_out, int out_size) {
    // metadata order: original_points(unused), data, w_qkv, pos_w1, pos_b1, pos_w2,
    // pos_b2, attn_w1, attn_b1, attn_w2, attn_b2, mlp_w1, mlp_b1, mlp_w2, mlp_b2,
    // mlp_w3, mlp_b3
    const float* data = (const float*)d_in[1];
    const float* wqkv = (const float*)d_in[2];
    const float* pw1  = (const float*)d_in[3];
    const float* pb1  = (const float*)d_in[4];
    const float* pw2  = (const float*)d_in[5];
    const float* pb2  = (const float*)d_in[6];
    const float* aw1  = (const float*)d_in[7];
    const float* ab1  = (const float*)d_in[8];
    const float* aw2  = (const float*)d_in[9];
    const float* ab2  = (const float*)d_in[10];
    const float* mw1  = (const float*)d_in[11];
    const float* mb1  = (const float*)d_in[12];
    const float* mw2  = (const float*)d_in[13];
    const float* mb2  = (const float*)d_in[14];
    const float* mw3  = (const float*)d_in[15];
    const float* mb3  = (const float*)d_in[16];
    float* out = (float*)d_out;

    const size_t smem = SMEM_FLOATS * sizeof(float);  // ~24 KB
    pt_kernel<<<NBLOCKS, NTHR, smem>>>(data, wqkv, pw1, pb1, pw2, pb2,
                                       aw1, ab1, aw2, ab2,
                                       mw1, mb1, mw2, mb2, mw3, mb3, out);
}

// round 6
// speedup vs baseline: 1.0711x; 1.0073x over previous
#include <cuda_runtime.h>

// Point-transformer fused kernel for GB300 (sm_103a).
// B*G = 16384 groups, 16 neighbors, dim 3. Warp = group.
// Thread = (i-pair ip, j-quad): owns 2 i's x 4 j's.
// Phase 2 packs f32x2 over h-pairs: i-side (a_i+b) and j-side (-a_j) stored
// h-pair-interleaved so ALL packed operands are natural register pairs
// (no dup movs); accumulators horizontally reduced once at the end.

#define GPB 4
#define NTHR 128
#define NBLOCKS (16384 / GPB)

// ---- shared memory layout (float offsets) ----
#define OFF_WQKV 0      // 27
#define OFF_PW1  32     // 192
#define OFF_PB1  224    // 64
#define OFF_W2H  288    // 256: [hp][8] = {d0h0,d0h1,d1h0,d1h1,d2h0,d2h1,pad,pad}
#define OFF_AW1D 544    // 72 dup pairs
#define OFF_AB1D 616    // 24 dup pairs
#define OFF_AW2D 640    // 72 dup pairs
#define OFF_AB2D 712    // 6 dup pairs
#define OFF_MB1  720    // 48
#define OFF_MB2  768    // 48
#define OFF_MW3  816    // 48
#define OFF_MB3  864    // 1
#define OFF_GRP  868
// per-group block (2352 floats):
#define GS_S2 0         // 8 jp * 132: [jp][hp][4] = {-a_j0[h0],-a_j0[h1],-a_j1[h0],-a_j1[h1]}
#define GS_TI 1056      // 8 ip * 132: [ip][hp][4] = {a_i0[h0]+b0,a_i0[h1]+b1,a_i1..}
#define GS_Q  2112      // q[i][d] 48
#define GS_NK 2160      // pb2[d]-k[i][d] 48
#define GS_KV 2208      // k+v 48
#define GS_SA 2256      // 48
#define GS_H1 2304      // 48
#define GRPSZ 2352
#define SMEM_FLOATS (OFF_GRP + GPB * GRPSZ)   // 10276 floats = 41.1 KB

__device__ __forceinline__ float2 add2(float2 a, float2 b) {
    float2 r;
    asm("add.rn.f32x2 %0, %1, %2;"
        : "=l"(*reinterpret_cast<unsigned long long*>(&r))
        : "l"(*reinterpret_cast<unsigned long long*>(&a)),
          "l"(*reinterpret_cast<unsigned long long*>(&b)));
    return r;
}
__device__ __forceinline__ float2 fma2(float2 a, float2 b, float2 c) {
    float2 r;
    asm("fma.rn.f32x2 %0, %1, %2, %3;"
        : "=l"(*reinterpret_cast<unsigned long long*>(&r))
        : "l"(*reinterpret_cast<unsigned long long*>(&a)),
          "l"(*reinterpret_cast<unsigned long long*>(&b)),
          "l"(*reinterpret_cast<unsigned long long*>(&c)));
    return r;
}

#define LOADW(PTR, OFF, N)                                        \
    for (int idx_ = tid; idx_ < (N); idx_ += NTHR) sm[(OFF) + idx_] = (PTR)[idx_];
#define LOADDUP(PTR, OFF, N2)                                     \
    for (int idx_ = tid; idx_ < (N2); idx_ += NTHR) sm[(OFF) + idx_] = (PTR)[idx_ >> 1];

__global__ __launch_bounds__(NTHR, 5)
void pt_kernel(const float* __restrict__ data,
               const float* __restrict__ wqkv,
               const float* __restrict__ pw1, const float* __restrict__ pb1,
               const float* __restrict__ pw2, const float* __restrict__ pb2,
               const float* __restrict__ aw1, const float* __restrict__ ab1,
               const float* __restrict__ aw2, const float* __restrict__ ab2,
               const float* __restrict__ mw1, const float* __restrict__ mb1,
               const float* __restrict__ mw2, const float* __restrict__ mb2,
               const float* __restrict__ mw3, const float* __restrict__ mb3,
               float* __restrict__ out)
{
    extern __shared__ float sm[];
    const int tid = threadIdx.x;
    const int g = tid >> 5;      // group = warp
    const int lg = tid & 31;
    const int ip = lg >> 2;      // i-pair (0..7): owns i = 2ip, 2ip+1
    const int quad = lg & 3;     // j-quad (0..3): owns j = 4quad..4quad+3

    // ---- stage weights ----
    LOADW(wqkv, OFF_WQKV, 27)
    LOADW(pw1, OFF_PW1, 192)
    LOADW(pb1, OFF_PB1, 64)
    // W2H: [hp][8] = {(w2[h0][d],w2[h1][d]) for d=0..2, pad, pad}
    for (int idx_ = tid; idx_ < 256; idx_ += NTHR) {
        const int hp = idx_ >> 3, r = idx_ & 7;
        const int d = r >> 1, s = r & 1;
        sm[OFF_W2H + idx_] = (r < 6) ? pw2[(2 * hp + s) * 3 + d] : 0.f;
    }
    LOADDUP(aw1, OFF_AW1D, 72)
    LOADDUP(ab1, OFF_AB1D, 24)
    LOADDUP(aw2, OFF_AW2D, 72)
    LOADDUP(ab2, OFF_AB2D, 6)
    LOADW(mb1, OFF_MB1, 48)
    LOADW(mb2, OFF_MB2, 48)
    LOADW(mw3, OFF_MW3, 48)
    LOADW(mb3, OFF_MB3, 1)

    float* grp = sm + OFF_GRP + g * GRPSZ;
    const int bg = blockIdx.x * GPB + g;

    // phase-1b work assignment: point p = lg&15, h-half hh = lg>>4
    const int p = lg & 15, hh = lg >> 4;
    const float* xp = data + (size_t)bg * 48 + p * 3;
    const float x0 = xp[0], x1 = xp[1], x2 = xp[2];

    __syncthreads();

    // ---- phase 1b: q,k,v for point p; S2 (negated a_j) and TI (a_i+b) ----
    const float* W = sm + OFF_WQKV;  // [3][9]: q 0-2, k 3-5, v 6-8
    {
        const float q0 = fmaf(x2, W[18 + 0], fmaf(x1, W[9 + 0], x0 * W[0]));
        const float q1 = fmaf(x2, W[18 + 1], fmaf(x1, W[9 + 1], x0 * W[1]));
        const float q2 = fmaf(x2, W[18 + 2], fmaf(x1, W[9 + 2], x0 * W[2]));
        const float k0 = fmaf(x2, W[18 + 3], fmaf(x1, W[9 + 3], x0 * W[3]));
        const float k1 = fmaf(x2, W[18 + 4], fmaf(x1, W[9 + 4], x0 * W[4]));
        const float k2 = fmaf(x2, W[18 + 5], fmaf(x1, W[9 + 5], x0 * W[5]));
        const float v0 = fmaf(x2, W[18 + 6], fmaf(x1, W[9 + 6], x0 * W[6]));
        const float v1 = fmaf(x2, W[18 + 7], fmaf(x1, W[9 + 7], x0 * W[7]));
        const float v2 = fmaf(x2, W[18 + 8], fmaf(x1, W[9 + 8], x0 * W[8]));
        if (hh == 0) {
            float* qW = grp + GS_Q + p * 3;
            qW[0] = q0; qW[1] = q1; qW[2] = q2;
            float* nkW = grp + GS_NK + p * 3;
            nkW[0] = pb2[0] - k0; nkW[1] = pb2[1] - k1; nkW[2] = pb2[2] - k2;
            float* kvW = grp + GS_KV + p * 3;
            kvW[0] = k0 + v0; kvW[1] = k1 + v1; kvW[2] = k2 + v2;
        }
    }
    {
        const float* P1 = sm + OFF_PW1 + hh * 32;
        const float* B1 = sm + OFF_PB1 + hh * 32;
        float* S2w = grp + GS_S2 + (p >> 1) * 132 + (p & 1) * 2 + hh * 64;
        float* TIw = grp + GS_TI + (p >> 1) * 132 + (p & 1) * 2 + hh * 64;
        #pragma unroll 8
        for (int h = 0; h < 32; h++) {
            const float a = fmaf(x2, P1[128 + h], fmaf(x1, P1[64 + h], x0 * P1[h]));
            const int off = ((h >> 1) << 2) + (h & 1);
            S2w[off] = -a;
            TIw[off] = a + B1[h];
        }
    }
    __syncwarp();   // group data is warp-private

    // ---- phase 2: packed-over-h rel_emb partials for 2 i x 4 j ----
    float2 reh[24];  // [(il*4+jl)*3 + d], packed over h-pair
    #pragma unroll
    for (int z = 0; z < 24; z++) reh[z] = make_float2(0.f, 0.f);
    {
        const float4* TI4 = (const float4*)(grp + GS_TI) + ip * 33;
        const float4* S4a = (const float4*)(grp + GS_S2) + (quad * 2) * 33;
        const float4* S4b = S4a + 33;
        const float4* W2H4 = (const float4*)(sm + OFF_W2H);
        #pragma unroll 2
        for (int hp = 0; hp < 32; hp++) {
            const float4 ti = TI4[hp];
            const float4 s0 = S4a[hp];
            const float4 s1 = S4b[hp];
            const float4 wab = W2H4[hp * 2];
            const float2 wc = *(const float2*)(sm + OFF_W2H + hp * 8 + 4);
            const float2 w0 = make_float2(wab.x, wab.y);
            const float2 w1 = make_float2(wab.z, wab.w);
            #pragma unroll
            for (int il = 0; il < 2; il++) {
                const float2 ai = il ? make_float2(ti.z, ti.w)
                                     : make_float2(ti.x, ti.y);
                float2 ee[4];
                ee[0] = add2(ai, make_float2(s0.x, s0.y));
                ee[1] = add2(ai, make_float2(s0.z, s0.w));
                ee[2] = add2(ai, make_float2(s1.x, s1.y));
                ee[3] = add2(ai, make_float2(s1.z, s1.w));
                #pragma unroll
                for (int jl = 0; jl < 4; jl++) {
                    float2 e = ee[jl];
                    e.x = fmaxf(e.x, 0.f); e.y = fmaxf(e.y, 0.f);
                    float2* r = reh + (il * 4 + jl) * 3;
                    r[0] = fma2(e, w0, r[0]);
                    r[1] = fma2(e, w1, r[1]);
                    r[2] = fma2(e, wc, r[2]);
                }
            }
        }
    }

    // ---- phase 3 prep: t = re + q_i + (pb2 - k_j); pack (i0,i1) pairs ----
    float qv[6];
    #pragma unroll
    for (int z = 0; z < 6; z++) qv[z] = grp[GS_Q + ip * 6 + z];
    float2 t2[12];  // [jl*3+d] : .x = i0, .y = i1
    #pragma unroll
    for (int jl = 0; jl < 4; jl++) {
        const int j = quad * 4 + jl;
        #pragma unroll
        for (int d = 0; d < 3; d++) {
            const float nkv = grp[GS_NK + j * 3 + d];
            const float2 r0 = reh[(0 * 4 + jl) * 3 + d];
            const float2 r1 = reh[(1 * 4 + jl) * 3 + d];
            t2[jl * 3 + d] = make_float2(r0.x + r0.y + qv[d] + nkv,
                                         r1.x + r1.y + qv[3 + d] + nkv);
        }
    }

    // ---- phase 3: attention MLP 3->12->3, packed over (i0,i1) ----
    float2 sim2[12];
    {
        const float2* ab2d = (const float2*)(sm + OFF_AB2D);
        const float2 b0 = ab2d[0], b1 = ab2d[1], b2 = ab2d[2];
        #pragma unroll
        for (int jl = 0; jl < 4; jl++) {
            sim2[jl * 3 + 0] = b0; sim2[jl * 3 + 1] = b1; sim2[jl * 3 + 2] = b2;
        }
    }
    {
        const float2* w1d = (const float2*)(sm + OFF_AW1D);
        const float2* b1d = (const float2*)(sm + OFF_AB1D);
        const float2* w2d = (const float2*)(sm + OFF_AW2D);
        #pragma unroll 2
        for (int c = 0; c < 12; c++) {
            const float2 w10 = w1d[c], w11 = w1d[12 + c], w12 = w1d[24 + c];
            const float2 bbd = b1d[c];
            const float2 w20 = w2d[c * 3 + 0], w21 = w2d[c * 3 + 1], w22 = w2d[c * 3 + 2];
            #pragma unroll
            for (int jl = 0; jl < 4; jl++) {
                float2 u = fma2(t2[jl * 3 + 2], w12,
                          fma2(t2[jl * 3 + 1], w11,
                          fma2(t2[jl * 3 + 0], w10, bbd)));
                u.x = fmaxf(u.x, 0.f); u.y = fmaxf(u.y, 0.f);
                sim2[jl * 3 + 0] = fma2(u, w20, sim2[jl * 3 + 0]);
                sim2[jl * 3 + 1] = fma2(u, w21, sim2[jl * 3 + 1]);
                sim2[jl * 3 + 2] = fma2(u, w22, sim2[jl * 3 + 2]);
            }
        }
    }

    // ---- phase 4: softmax over 16 j = 4 local + reduce over 4 quad lanes ----
    #pragma unroll
    for (int il = 0; il < 2; il++) {
        float agg[3];
        #pragma unroll
        for (int d = 0; d < 3; d++) {
            float sv[4], tv[4];
            #pragma unroll
            for (int jl = 0; jl < 4; jl++) {
                sv[jl] = il ? sim2[jl * 3 + d].y : sim2[jl * 3 + d].x;
                tv[jl] = il ? t2[jl * 3 + d].y : t2[jl * 3 + d].x;
            }
            float pm = fmaxf(fmaxf(sv[0], sv[1]), fmaxf(sv[2], sv[3]));
            pm = fmaxf(pm, __shfl_xor_sync(0xffffffffu, pm, 1));
            pm = fmaxf(pm, __shfl_xor_sync(0xffffffffu, pm, 2));
            const float qd = qv[il * 3 + d];
            float s = 0.f, acc = 0.f;
            #pragma unroll
            for (int jl = 0; jl < 4; jl++) {
                const float pr = __expf(sv[jl] - pm);
                s += pr;
                // v_ij = v_j + re = t + (k_j+v_j) - q_i
                const float vij = tv[jl] + grp[GS_KV + (quad * 4 + jl) * 3 + d] - qd;
                acc = fmaf(pr, vij, acc);
            }
            s   += __shfl_xor_sync(0xffffffffu, s, 1);
            s   += __shfl_xor_sync(0xffffffffu, s, 2);
            acc += __shfl_xor_sync(0xffffffffu, acc, 1);
            acc += __shfl_xor_sync(0xffffffffu, acc, 2);
            agg[d] = __fdividef(acc, s);
        }
        if (quad == 0) {
            float* saW = grp + GS_SA + (ip * 2 + il) * 3;
            saW[0] = agg[0]; saW[1] = agg[1]; saW[2] = agg[2];
        }
    }
    __syncwarp();

    // ---- phase 5: MLP head 48->48->48->1; lanes 0..23 own float2 col pairs ----
    const float* saS = grp + GS_SA;
    const int col = 2 * lg;
    float2 h1 = make_float2(0.f, 0.f);
    if (lg < 24) {
        h1.x = sm[OFF_MB1 + col]; h1.y = sm[OFF_MB1 + col + 1];
        #pragma unroll 4
        for (int kk = 0; kk < 48; kk++) {
            const float svv = saS[kk];
            const float2 w = __ldg((const float2*)(mw1 + kk * 48 + col));
            h1.x = fmaf(svv, w.x, h1.x);
            h1.y = fmaf(svv, w.y, h1.y);
        }
        h1.x = fmaxf(h1.x, 0.f); h1.y = fmaxf(h1.y, 0.f);
        *(float2*)(grp + GS_H1 + col) = h1;
    }
    __syncwarp();

    const float* h1S = grp + GS_H1;
    float pw = 0.f;
    if (lg < 24) {
        float2 h2 = make_float2(sm[OFF_MB2 + col], sm[OFF_MB2 + col + 1]);
        #pragma unroll 4
        for (int kk = 0; kk < 48; kk++) {
            const float hv = h1S[kk];
            const float2 w = __ldg((const float2*)(mw2 + kk * 48 + col));
            h2.x = fmaf(hv, w.x, h2.x);
            h2.y = fmaf(hv, w.y, h2.y);
        }
        h2.x = fmaxf(h2.x, 0.f); h2.y = fmaxf(h2.y, 0.f);
        pw = fmaf(h2.y, sm[OFF_MW3 + col + 1], h2.x * sm[OFF_MW3 + col]);
    }
    pw += __shfl_xor_sync(0xffffffffu, pw, 16);
    pw += __shfl_xor_sync(0xffffffffu, pw, 8);
    pw += __shfl_xor_sync(0xffffffffu, pw, 4);
    pw += __shfl_xor_sync(0xffffffffu, pw, 2);
    pw += __shfl_xor_sync(0xffffffffu, pw, 1);
    if (lg == 0) out[bg] = pw + sm[OFF_MB3];
}

extern "C" void kernel_launch(void* const* d_in, const int* in_sizes, int n_in,
                              void* d_out, int out_size) {
    // metadata order: original_points(unused), data, w_qkv, pos_w1, pos_b1, pos_w2,
    // pos_b2, attn_w1, attn_b1, attn_w2, attn_b2, mlp_w1, mlp_b1, mlp_w2, mlp_b2,
    // mlp_w3, mlp_b3
    const float* data = (const float*)d_in[1];
    const float* wqkv = (const float*)d_in[2];
    const float* pw1  = (const float*)d_in[3];
    const float* pb1  = (const float*)d_in[4];
    const float* pw2  = (const float*)d_in[5];
    const float* pb2  = (const float*)d_in[6];
    const float* aw1  = (const float*)d_in[7];
    const float* ab1  = (const float*)d_in[8];
    const float* aw2  = (const float*)d_in[9];
    const float* ab2  = (const float*)d_in[10];
    const float* mw1  = (const float*)d_in[11];
    const float* mb1  = (const float*)d_in[12];
    const float* mw2  = (const float*)d_in[13];
    const float* mb2  = (const float*)d_in[14];
    const float* mw3  = (const float*)d_in[15];
    const float* mb3  = (const float*)d_in[16];
    float* out = (float*)d_out;

    const size_t smem = SMEM_FLOATS * sizeof(float);  // ~41.1 KB
    pt_kernel<<<NBLOCKS, NTHR, smem>>>(data, wqkv, pw1, pb1, pw2, pb2,
                                       aw1, ab1, aw2, ab2,
                                       mw1, mb1, mw2, mb2, mw3, mb3, out);
}